// round 5
// baseline (speedup 1.0000x reference)
#include <cuda_runtime.h>
#include <cuda_bf16.h>
#include <math.h>

#define NPIX     768
#define NP       (NPIX * NPIX)     // 589824 floats per basis term
#define NP4      (NP / 4)          // 147456 float4 per basis term
#define ROW4     (NPIX / 4)        // 192 float4 per row
#define NTERMS   128
#define PPSZ     256
#define THREADS  288               // 3 rows x 96 float4 = 288 float4 per region
#define HALFJ4   96                // 384 floats / 4

// ---------------------------------------------------------------------------
// Fused kernel: each block streams basis rows I in [3*Cb, 3*Cb+3), columns
// J in [Jhalf*384, Jhalf*384+384), reduces over the 128 terms into registers,
// stages the 3x384 latent tile in shared memory, then computes the 128 CLIMB
// patch outputs for that tile. Patches are disjoint 3x3 tiles, so no
// cross-block communication is needed.
// ---------------------------------------------------------------------------
__global__ void __launch_bounds__(THREADS) fused_climb_kernel(
    const float4* __restrict__ basis4,
    const float*  __restrict__ coeffs,
    const float*  __restrict__ wavel_ptr,
    float*        __restrict__ out)
{
    __shared__ float sc[NTERMS];
    __shared__ float tile[3][384];   // latent band: tile[c][localJ]

    int t = threadIdx.x;
    if (t < NTERMS) sc[t] = coeffs[t];
    __syncthreads();

    int Cb    = blockIdx.x >> 1;     // 0..255
    int Jhalf = blockIdx.x & 1;      // 0..1

    // This thread's float4 slot within the 3x384 region
    int row  = t / HALFJ4;           // 0..2  (c index / I-row within band)
    int col4 = t % HALFJ4;           // 0..95

    const float4* p = basis4
        + (size_t)(3 * Cb + row) * ROW4
        + (size_t)Jhalf * HALFJ4
        + col4;

    float4 acc = make_float4(0.f, 0.f, 0.f, 0.f);

#pragma unroll 8
    for (int n = 0; n < NTERMS; n++) {
        float4 v = __ldcs(p + (size_t)n * NP4);   // streaming: no reuse
        float  c = sc[n];
        acc.x = fmaf(v.x, c, acc.x);
        acc.y = fmaf(v.y, c, acc.y);
        acc.z = fmaf(v.z, c, acc.z);
        acc.w = fmaf(v.w, c, acc.w);
    }

    // Stage latent band in shared memory
    *reinterpret_cast<float4*>(&tile[row][col4 * 4]) = acc;
    __syncthreads();

    // ---- CLIMB patch compute: threads 0..127 each handle one patch ----
    if (t < 128) {
        int pch = t;                         // local patch index (J direction)
        // z[3r+c] = latent[I = 3Cb+c, J = Jbase + 3*pch + r] = tile[c][3*pch+r]
        float z[9];
#pragma unroll
        for (int c = 0; c < 3; c++) {
#pragma unroll
            for (int r = 0; r < 3; r++) {
                z[3 * r + c] = tile[c][3 * pch + r];
            }
        }

        // LSQ plane fit over unit 3x3 grid (orthogonal regressors):
        //   a = sum z*(x-1/2)/1.5,  b = sum z*(y-1/2)/1.5,
        //   cc = mean(z) - a/2 - b/2
        float S = 0.f, Sx = 0.f, Sy = 0.f;
        bool allpos = true, allnonpos = true, anyzero = false;
#pragma unroll
        for (int k = 0; k < 9; k++) {
            float v  = z[k];
            float xk = 0.5f * (float)(k % 3);
            float yk = 0.5f * (float)(k / 3);
            S  += v;
            Sx += v * xk;
            Sy += v * yk;
            allpos    = allpos    && (v > 0.f);
            allnonpos = allnonpos && (v <= 0.f);
            anyzero   = anyzero   || (v == 0.f);
        }
        float mean = S * (1.f / 9.f);
        float a  = (Sx - 0.5f * S) * (1.f / 1.5f);
        float b  = (Sy - 0.5f * S) * (1.f / 1.5f);
        float cc = mean - 0.5f * a - 0.5f * b;

        const float EPSF = 1e-15f;
        if (a  == 0.f) a  = EPSF;
        if (b  == 0.f) b  = EPSF;
        if (cc == 0.f) cc = EPSF;

        float x1 = (-b - cc) / a;
        float x2 = (-cc) / a;
        float lo = fminf(x1, x2);
        float hi = fmaxf(x1, x2);
        x1 = fmaxf(lo, 0.f);
        x2 = fminf(hi, 1.f);

        float ncb = (-cc) / b;
        float ab  = a / b;
        float d = x1 + ncb * x2 - 0.5f * ab * x2 * x2
                     - ncb * x1 + 0.5f * ab * x1 * x1;

        d = (d >= 0.5f)   ? d : (1.0f - d);
        d = (mean >= 0.f) ? d : (1.0f - d);
        if (allpos)    d = 1.0f;
        if (allnonpos) d = 0.0f;
        if (anyzero)   d = (d > 0.f) ? 1.0f : 0.0f;
        d = fminf(fmaxf(d, 0.f), 1.f);

        // opd = pi*d * wavel / (2*pi)
        float wl = *wavel_ptr;
        int Rb = Jhalf * 128 + pch;
        out[Cb * PPSZ + Rb] = ((float)M_PI * d) * wl * (1.0f / (2.0f * (float)M_PI));
    }
}

extern "C" void kernel_launch(void* const* d_in, const int* in_sizes, int n_in,
                              void* d_out, int out_size)
{
    const float4* basis4 = reinterpret_cast<const float4*>(d_in[0]); // (128,768,768) f32
    const float*  coeffs = reinterpret_cast<const float*>(d_in[1]);  // (128,)
    const float*  wavel  = reinterpret_cast<const float*>(d_in[2]);  // scalar
    float*        out    = reinterpret_cast<float*>(d_out);          // (256,256) f32

    (void)in_sizes; (void)n_in; (void)out_size;

    fused_climb_kernel<<<512, THREADS>>>(basis4, coeffs, wavel, out);
}

// round 6
// speedup vs baseline: 1.0536x; 1.0536x over previous
#include <cuda_runtime.h>
#include <cuda_bf16.h>
#include <math.h>

#define NPIX   768
#define NP     (NPIX * NPIX)       // 589824
#define NP4    (NP / 4)            // 147456
#define NTERMS 128
#define PPSZ   256
#define NOUT   (PPSZ * PPSZ)       // 65536

// Scratch for latent^T: L[I][J] = sum_n basis[n, I, J] * coeffs[n]  (2.36 MB)
__device__ float g_latent[NP];

// ---------------------------------------------------------------------------
// Kernel 1 (unchanged from the 46.8us/6.45TB/s version): HBM-streaming
// weighted reduction over the 128 basis terms. Thread t owns float4-pixel
// index t; fully coalesced 128-bit loads, unroll 8 for MLP.
// ---------------------------------------------------------------------------
__global__ void __launch_bounds__(256) latent_kernel(
    const float4* __restrict__ basis4,
    const float*  __restrict__ coeffs)
{
    __shared__ float sc[NTERMS];
    if (threadIdx.x < NTERMS) sc[threadIdx.x] = coeffs[threadIdx.x];
    __syncthreads();

    int idx = blockIdx.x * blockDim.x + threadIdx.x;   // 0 .. NP4-1
    if (idx >= NP4) return;

    const float4* p = basis4 + idx;
    float4 acc = make_float4(0.f, 0.f, 0.f, 0.f);

#pragma unroll 8
    for (int n = 0; n < NTERMS; n++) {
        float4 v = p[(size_t)n * NP4];
        float  c = sc[n];
        acc.x = fmaf(v.x, c, acc.x);
        acc.y = fmaf(v.y, c, acc.y);
        acc.z = fmaf(v.z, c, acc.z);
        acc.w = fmaf(v.w, c, acc.w);
    }
    reinterpret_cast<float4*>(g_latent)[idx] = acc;
}

// ---------------------------------------------------------------------------
// Kernel 2: CLIMB area per 3x3 patch.
// 512 blocks x 128 threads: whole grid resident in one wave (4-warp blocks),
// no block-quantization tail. All 9 loads front-batched (MLP=9) before the
// dependent LSQ/area math.
// out[Cb*256 + Rb] from z[3r+c] = L[(3Cb+c)*768 + 3Rb+r]
// ---------------------------------------------------------------------------
__global__ void __launch_bounds__(128) climb_kernel(
    float* __restrict__ out,
    const float* __restrict__ wavel_ptr)
{
    int o = blockIdx.x * 128 + threadIdx.x;
    int Cb = o >> 8;
    int Rb = o & 255;

    const float* base = g_latent + (3 * Cb) * NPIX + 3 * Rb;

    // Front-batch all 9 independent loads (k = 3r+c maps to base[c*768 + r])
    float z0 = __ldg(base + 0 * NPIX + 0);
    float z1 = __ldg(base + 1 * NPIX + 0);
    float z2 = __ldg(base + 2 * NPIX + 0);
    float z3 = __ldg(base + 0 * NPIX + 1);
    float z4 = __ldg(base + 1 * NPIX + 1);
    float z5 = __ldg(base + 2 * NPIX + 1);
    float z6 = __ldg(base + 0 * NPIX + 2);
    float z7 = __ldg(base + 1 * NPIX + 2);
    float z8 = __ldg(base + 2 * NPIX + 2);

    float zz[9] = {z0, z1, z2, z3, z4, z5, z6, z7, z8};

    // LSQ plane fit over unit 3x3 grid (orthogonal regressors):
    //   a = sum z*(x-1/2)/1.5,  b = sum z*(y-1/2)/1.5,
    //   c = mean(z) - a/2 - b/2
    float S = 0.f, Sx = 0.f, Sy = 0.f;
    bool allpos = true, allnonpos = true, anyzero = false;
#pragma unroll
    for (int k = 0; k < 9; k++) {
        float v  = zz[k];
        float xk = 0.5f * (float)(k % 3);
        float yk = 0.5f * (float)(k / 3);
        S  += v;
        Sx += v * xk;
        Sy += v * yk;
        allpos    = allpos    && (v > 0.f);
        allnonpos = allnonpos && (v <= 0.f);
        anyzero   = anyzero   || (v == 0.f);
    }
    float mean = S * (1.f / 9.f);
    float a  = (Sx - 0.5f * S) * (1.f / 1.5f);
    float b  = (Sy - 0.5f * S) * (1.f / 1.5f);
    float cc = mean - 0.5f * a - 0.5f * b;

    const float EPSF = 1e-15f;
    if (a  == 0.f) a  = EPSF;
    if (b  == 0.f) b  = EPSF;
    if (cc == 0.f) cc = EPSF;

    float x1 = (-b - cc) / a;
    float x2 = (-cc) / a;
    float lo = fminf(x1, x2);
    float hi = fmaxf(x1, x2);
    x1 = fmaxf(lo, 0.f);
    x2 = fminf(hi, 1.f);

    float ncb = (-cc) / b;
    float ab  = a / b;
    float d = x1 + ncb * x2 - 0.5f * ab * x2 * x2
                 - ncb * x1 + 0.5f * ab * x1 * x1;

    d = (d >= 0.5f)   ? d : (1.0f - d);
    d = (mean >= 0.f) ? d : (1.0f - d);
    if (allpos)    d = 1.0f;
    if (allnonpos) d = 0.0f;
    if (anyzero)   d = (d > 0.f) ? 1.0f : 0.0f;
    d = fminf(fmaxf(d, 0.f), 1.f);

    // opd = pi*d * wavel / (2*pi)
    float wl = *wavel_ptr;
    out[o] = ((float)M_PI * d) * wl * (1.0f / (2.0f * (float)M_PI));
}

extern "C" void kernel_launch(void* const* d_in, const int* in_sizes, int n_in,
                              void* d_out, int out_size)
{
    const float4* basis4 = reinterpret_cast<const float4*>(d_in[0]); // (128,768,768) f32
    const float*  coeffs = reinterpret_cast<const float*>(d_in[1]);  // (128,)
    const float*  wavel  = reinterpret_cast<const float*>(d_in[2]);  // scalar
    float*        out    = reinterpret_cast<float*>(d_out);          // (256,256) f32

    (void)in_sizes; (void)n_in; (void)out_size;

    latent_kernel<<<(NP4 + 255) / 256, 256>>>(basis4, coeffs);
    climb_kernel<<<NOUT / 128, 128>>>(out, wavel);
}